// round 10
// baseline (speedup 1.0000x reference)
#include <cuda_runtime.h>

#define NQ 10
#define NL 4
#define BATCH 4096
#define FULL 0xFFFFFFFFu

typedef unsigned long long u64;

// ---- f32x2 packed-math primitives (sm_100+/sm_103a) ----
__device__ __forceinline__ u64 pk2(float lo, float hi) {
    u64 r; asm("mov.b64 %0,{%1,%2};" : "=l"(r) : "f"(lo), "f"(hi)); return r;
}
__device__ __forceinline__ void upk2(u64 a, float& lo, float& hi) {
    asm("mov.b64 {%0,%1},%2;" : "=f"(lo), "=f"(hi) : "l"(a));
}
__device__ __forceinline__ u64 fma2(u64 a, u64 b, u64 c) {
    u64 r; asm("fma.rn.f32x2 %0,%1,%2,%3;" : "=l"(r) : "l"(a), "l"(b), "l"(c)); return r;
}
__device__ __forceinline__ u64 mul2(u64 a, u64 b) {
    u64 r; asm("mul.rn.f32x2 %0,%1,%2;" : "=l"(r) : "l"(a), "l"(b)); return r;
}
__device__ __forceinline__ u64 swp2(u64 a) {
    float x, y; upk2(a, x, y); return pk2(y, x);
}
__device__ __forceinline__ u64 shflx2(u64 a, int m) {
    float x, y; upk2(a, x, y);
    x = __shfl_xor_sync(FULL, x, m);
    y = __shfl_xor_sync(FULL, y, m);
    return pk2(x, y);
}
__device__ __forceinline__ u64 shfli2(u64 a, int src) {
    float x, y; upk2(a, x, y);
    x = __shfl_sync(FULL, x, src);
    y = __shfl_sync(FULL, y, src);
    return pk2(x, y);
}

// ---- grid-uniform gate-constant table (written by prep kernel) ----
// lane[q]  (q0..q4): {cy, sy, cz, sz}
// jc[q-5]  (q5..q8): {cyv, syv, nsyv, czv, szv, nszv}  (packed dup pairs)
// pk[]     (q9):     {cyv, svec(-sy,sy), szpk(sz,-sz), szpkn(-sz,sz), czv}
struct GateTab {
    float4 lane[5];
    u64 jc[4][6];
    u64 pk[6];
};
__device__ GateTab g_tab[NL];

__global__ void prep_kernel(const float* __restrict__ params) {
    const int t = threadIdx.x;
    if (t >= NL * NQ) return;
    const int l = t / NQ, q = t % NQ;
    const float* p = params + l * (2 * NQ);
    const float hy = 0.5f * p[q];
    const float hz = 0.5f * p[NQ + q];
    float cy, sy, cz, sz;
    __sincosf(hy, &sy, &cy);
    __sincosf(hz, &sz, &cz);
    if (q <= 4) {
        g_tab[l].lane[q] = make_float4(cy, sy, cz, sz);
    } else if (q <= 8) {
        u64* jc = g_tab[l].jc[q - 5];
        jc[0] = pk2(cy, cy);  jc[1] = pk2(sy, sy);  jc[2] = pk2(-sy, -sy);
        jc[3] = pk2(cz, cz);  jc[4] = pk2(sz, sz);  jc[5] = pk2(-sz, -sz);
    } else {
        u64* pk = g_tab[l].pk;
        pk[0] = pk2(cy, cy);
        pk[1] = pk2(-sy, sy);
        pk[2] = pk2(sz, -sz);
        pk[3] = pk2(-sz, sz);
        pk[4] = pk2(cz, cz);
        pk[5] = 0ull;
    }
}

// State layout: amplitude index idx = (lane << 5) | (j << 1) | h, j = 0..15, h = 0/1.
//   qubit 0..4  -> lane bit (4 - q)
//   qubit 5..8  -> j bit    (8 - q)
//   qubit 9     -> packed half h (lo = 0, hi = 1)

// ---- fused RY (+optional RZ) on a j-bit qubit (q5..q8) ----
template<int JB, bool RZ>
__device__ __forceinline__ void ryrz_j(u64 (&Pr)[16], u64 (&Pi)[16], const u64* __restrict__ jc) {
    const u64 cyv  = __ldg(jc + 0);
    const u64 syv  = __ldg(jc + 1);
    const u64 nsyv = __ldg(jc + 2);
    u64 czv = 0, szv = 0, nszv = 0;
    if constexpr (RZ) { czv = __ldg(jc + 3); szv = __ldg(jc + 4); nszv = __ldg(jc + 5); }
#pragma unroll
    for (int j0 = 0; j0 < 16; ++j0) {
        if (j0 & (1 << JB)) continue;
        const int j1 = j0 | (1 << JB);
        u64 t0r = fma2(cyv, Pr[j0], mul2(nsyv, Pr[j1]));
        u64 t0i = fma2(cyv, Pi[j0], mul2(nsyv, Pi[j1]));
        u64 t1r = fma2(syv, Pr[j0], mul2(cyv, Pr[j1]));
        u64 t1i = fma2(syv, Pi[j0], mul2(cyv, Pi[j1]));
        if constexpr (RZ) {
            Pr[j0] = fma2(czv, t0r, mul2(szv,  t0i));
            Pi[j0] = fma2(czv, t0i, mul2(nszv, t0r));
            Pr[j1] = fma2(czv, t1r, mul2(nszv, t1i));
            Pi[j1] = fma2(czv, t1i, mul2(szv,  t1r));
        } else {
            Pr[j0] = t0r; Pi[j0] = t0i;
            Pr[j1] = t1r; Pi[j1] = t1i;
        }
    }
}

// ---- fused RY (+optional RZ) on qubit 9 (the packed dimension) ----
template<bool RZ>
__device__ __forceinline__ void ryrz_pk(u64 (&Pr)[16], u64 (&Pi)[16], const u64* __restrict__ pk) {
    const u64 cyv  = __ldg(pk + 0);
    const u64 svec = __ldg(pk + 1);
    u64 szpk = 0, szpkn = 0, czv = 0;
    if constexpr (RZ) { szpk = __ldg(pk + 2); szpkn = __ldg(pk + 3); czv = __ldg(pk + 4); }
#pragma unroll
    for (int j = 0; j < 16; ++j) {
        u64 sr = swp2(Pr[j]);
        u64 si = swp2(Pi[j]);
        u64 tr = fma2(cyv, Pr[j], mul2(svec, sr));
        u64 ti = fma2(cyv, Pi[j], mul2(svec, si));
        if constexpr (RZ) {
            Pr[j] = fma2(czv, tr, mul2(szpk,  ti));
            Pi[j] = fma2(czv, ti, mul2(szpkn, tr));
        } else {
            Pr[j] = tr; Pi[j] = ti;
        }
    }
}

// ---- fused RY (+optional RZ) on a lane-bit qubit (q0..q4) ----
template<int LB, bool RZ>
__device__ __forceinline__ void ryrz_lane(u64 (&Pr)[16], u64 (&Pi)[16],
                                          const float4* __restrict__ lc, int lane) {
    const float4 t = __ldg(lc);
    const int m = 1 << LB;
    const bool hi = (lane & m) != 0;
    const float ss = hi ?  t.y : -t.y;
    const float pz = hi ?  t.w : -t.w;
    const u64 cyv = pk2(t.x, t.x), ssv = pk2(ss, ss);
    const u64 czv = pk2(t.z, t.z), pzv = pk2(pz, pz), npzv = pk2(-pz, -pz);
#pragma unroll
    for (int j = 0; j < 16; ++j) {
        u64 prv = shflx2(Pr[j], m);
        u64 piv = shflx2(Pi[j], m);
        u64 tr = fma2(cyv, Pr[j], mul2(ssv, prv));
        u64 ti = fma2(cyv, Pi[j], mul2(ssv, piv));
        if constexpr (RZ) {
            Pr[j] = fma2(czv, tr, mul2(npzv, ti));
            Pi[j] = fma2(czv, ti, mul2(pzv,  tr));
        } else {
            Pr[j] = tr; Pi[j] = ti;
        }
    }
}

// ---- composed CNOT(0,1)(1,2)(2,3)(3,4): single lane permutation ----
__device__ __forceinline__ void cnot_lane_ring(u64 (&Pr)[16], u64 (&Pi)[16], int lane) {
    const int src = lane ^ ((lane >> 1) & 0xF);
#pragma unroll
    for (int j = 0; j < 16; ++j) {
        Pr[j] = shfli2(Pr[j], src);
        Pi[j] = shfli2(Pi[j], src);
    }
}

__device__ __forceinline__ void cnot_lj_c4(u64 (&Pr)[16], u64 (&Pi)[16], int lane) {
    if (lane & 1) {
#pragma unroll
        for (int j = 0; j < 8; ++j) {
            u64 t = Pr[j]; Pr[j] = Pr[j | 8]; Pr[j | 8] = t;
            u64 u = Pi[j]; Pi[j] = Pi[j | 8]; Pi[j | 8] = u;
        }
    }
}

template<int JC, int JT>
__device__ __forceinline__ void cnot_jj(u64 (&Pr)[16], u64 (&Pi)[16]) {
#pragma unroll
    for (int j = 0; j < 16; ++j) {
        if ((j & (1 << JC)) && !(j & (1 << JT))) {
            const int j1 = j | (1 << JT);
            u64 t = Pr[j]; Pr[j] = Pr[j1]; Pr[j1] = t;
            u64 u = Pi[j]; Pi[j] = Pi[j1]; Pi[j1] = u;
        }
    }
}

__device__ __forceinline__ void cnot_jp_c8(u64 (&Pr)[16], u64 (&Pi)[16]) {
#pragma unroll
    for (int j = 1; j < 16; j += 2) {
        Pr[j] = swp2(Pr[j]);
        Pi[j] = swp2(Pi[j]);
    }
}

__device__ __forceinline__ void cnot_pl_c9(u64 (&Pr)[16], u64 (&Pi)[16]) {
#pragma unroll
    for (int j = 0; j < 16; ++j) {
        float x, y; upk2(Pr[j], x, y);
        y = __shfl_xor_sync(FULL, y, 16);
        Pr[j] = pk2(x, y);
        float u, v; upk2(Pi[j], u, v);
        v = __shfl_xor_sync(FULL, v, 16);
        Pi[j] = pk2(u, v);
    }
}

template<bool RZ>
__device__ __forceinline__ void layer_rotations(u64 (&Pr)[16], u64 (&Pi)[16],
                                                const GateTab* __restrict__ tab, int lane) {
    ryrz_lane<4, RZ>(Pr, Pi, &tab->lane[0], lane);
    ryrz_lane<3, RZ>(Pr, Pi, &tab->lane[1], lane);
    ryrz_lane<2, RZ>(Pr, Pi, &tab->lane[2], lane);
    ryrz_lane<1, RZ>(Pr, Pi, &tab->lane[3], lane);
    ryrz_lane<0, RZ>(Pr, Pi, &tab->lane[4], lane);
    ryrz_j<3, RZ>(Pr, Pi, tab->jc[0]);
    ryrz_j<2, RZ>(Pr, Pi, tab->jc[1]);
    ryrz_j<1, RZ>(Pr, Pi, tab->jc[2]);
    ryrz_j<0, RZ>(Pr, Pi, tab->jc[3]);
    ryrz_pk<RZ>(Pr, Pi, tab->pk);
}

__device__ __forceinline__ void layer_cnots(u64 (&Pr)[16], u64 (&Pi)[16], int lane) {
    cnot_lane_ring(Pr, Pi, lane);   // CNOT(0,1)(1,2)(2,3)(3,4) composed
    cnot_lj_c4(Pr, Pi, lane);       // CNOT(4,5)
    cnot_jj<3, 2>(Pr, Pi);          // CNOT(5,6)
    cnot_jj<2, 1>(Pr, Pi);          // CNOT(6,7)
    cnot_jj<1, 0>(Pr, Pi);          // CNOT(7,8)
    cnot_jp_c8(Pr, Pi);             // CNOT(8,9)
    cnot_pl_c9(Pr, Pi);             // CNOT(9,0)
}

__global__ void __launch_bounds__(256, 3)
pqc_kernel(const float* __restrict__ x, const float* __restrict__ params,
           float* __restrict__ out) {
    const int warp = (int)((blockIdx.x * blockDim.x + threadIdx.x) >> 5);
    const int lane = (int)(threadIdx.x & 31);

    // ======== init: encoding RY(x) fused with layer-0 RY(θy) + RZ(θz) ========
    // Lane-qubit (q0..q4) trig is consumed immediately to keep the live set small.
    float lf = 1.0f, phL = 0.0f;
#pragma unroll
    for (int q = 0; q <= 4; ++q) {
        const float hy = 0.5f * (__ldg(x + warp * NQ + q) + __ldg(params + q));
        const float tzq = 0.5f * __ldg(params + NQ + q);
        float cq, sq;
        __sincosf(hy, &sq, &cq);
        if ((lane >> (4 - q)) & 1) { lf *= sq; phL += tzq; }
        else                       { lf *= cq; phL -= tzq; }
    }

    float cs[5], ss[5], tzs[5];
#pragma unroll
    for (int q = 5; q <= 9; ++q) {
        const float hy = 0.5f * (__ldg(x + warp * NQ + q) + __ldg(params + q));
        __sincosf(hy, &ss[q - 5], &cs[q - 5]);
        tzs[q - 5] = 0.5f * __ldg(params + NQ + q);
    }

    float c9z, s9z;
    __sincosf(tzs[4], &s9z, &c9z);

    u64 Pr[16], Pi[16];
#pragma unroll
    for (int j = 0; j < 16; ++j) {
        float f = lf, ph = phL;           // j bit JB -> qubit (8 - JB)
#pragma unroll
        for (int JB = 0; JB < 4; ++JB) {
            const int i = 3 - JB;         // qubit (5 + i)
            if ((j >> JB) & 1) { f *= ss[i]; ph += tzs[i]; }
            else               { f *= cs[i]; ph -= tzs[i]; }
        }
        float cp, sp;
        __sincosf(ph, &sp, &cp);
        const float re0 = fmaf(cp, c9z,  sp * s9z);
        const float im0 = fmaf(sp, c9z, -(cp * s9z));
        const float re1 = fmaf(cp, c9z, -(sp * s9z));
        const float im1 = fmaf(sp, c9z,  cp * s9z);
        const float f0 = f * cs[4], f1 = f * ss[4];
        Pr[j] = pk2(f0 * re0, f1 * re1);
        Pi[j] = pk2(f0 * im0, f1 * im1);
    }
    // layer 0's CNOT ring still applies:
    layer_cnots(Pr, Pi, lane);

    // ======== middle layers ========
#pragma unroll 1
    for (int l = 1; l < NL - 1; ++l) {
        layer_rotations<true>(Pr, Pi, &g_tab[l], lane);
        layer_cnots(Pr, Pi, lane);
    }

    // ======== last layer: RY only; RZ + CNOT ring folded into measurement ========
    layer_rotations<false>(Pr, Pi, &g_tab[NL - 1], lane);

    // ======== measurement with CNOT-ring permutation folded into sign parities ========
    float psum = 0.0f, A = 0.0f;
    float S5 = 0.0f, S6 = 0.0f, S7 = 0.0f, S8 = 0.0f;
#pragma unroll
    for (int j = 0; j < 16; ++j) {
        u64 pp = fma2(Pr[j], Pr[j], mul2(Pi[j], Pi[j]));
        float plo, phi; upk2(pp, plo, phi);
        const float T = plo + phi;
        const float D = plo - phi;
        psum += T;
        A  += (__popc(j)      & 1) ? -D : D;
        S5 += ((j >> 3)       & 1) ? -T : T;
        S6 += (__popc(j >> 2) & 1) ? -T : T;
        S7 += (__popc(j >> 1) & 1) ? -T : T;
        S8 += (__popc(j)      & 1) ? -T : T;
    }

    const int lp = __popc(lane) & 1;
    float resv[NQ];
    resv[0] = ((lp ^ (lane >> 4)) & 1) ? -A : A;
    resv[1] = (__popc(lane >> 3) & 1) ? -psum : psum;
    resv[2] = (__popc(lane >> 2) & 1) ? -psum : psum;
    resv[3] = (__popc(lane >> 1) & 1) ? -psum : psum;
    resv[4] = lp ? -psum : psum;
    resv[5] = lp ? -S5 : S5;
    resv[6] = lp ? -S6 : S6;
    resv[7] = lp ? -S7 : S7;
    resv[8] = lp ? -S8 : S8;
    resv[9] = lp ? -A  : A;

#pragma unroll
    for (int q = 0; q < NQ; ++q) {
        float v = resv[q];
#pragma unroll
        for (int o = 16; o > 0; o >>= 1) v += __shfl_xor_sync(FULL, v, o);
        resv[q] = v;
    }

    if (lane == 0) {
#pragma unroll
        for (int q = 0; q < NQ; ++q)
            out[warp * NQ + q] = resv[q];
    }
}

extern "C" void kernel_launch(void* const* d_in, const int* in_sizes, int n_in,
                              void* d_out, int out_size) {
    const float* x      = (const float*)d_in[0];   // [4096, 10] float32
    const float* params = (const float*)d_in[1];   // [4, 20] float32
    float* out          = (float*)d_out;           // [4096, 10] float32
    (void)in_sizes; (void)n_in; (void)out_size;
    prep_kernel<<<1, 64>>>(params);
    pqc_kernel<<<BATCH / 8, 256>>>(x, params, out);
}

// round 12
// speedup vs baseline: 1.1944x; 1.1944x over previous
#include <cuda_runtime.h>

#define NQ 10
#define NL 4
#define BATCH 4096
#define FULL 0xFFFFFFFFu

typedef unsigned long long u64;

// ---- f32x2 packed-math primitives (sm_100+/sm_103a) ----
__device__ __forceinline__ u64 pk2(float lo, float hi) {
    u64 r; asm("mov.b64 %0,{%1,%2};" : "=l"(r) : "f"(lo), "f"(hi)); return r;
}
__device__ __forceinline__ void upk2(u64 a, float& lo, float& hi) {
    asm("mov.b64 {%0,%1},%2;" : "=f"(lo), "=f"(hi) : "l"(a));
}
__device__ __forceinline__ u64 fma2(u64 a, u64 b, u64 c) {
    u64 r; asm("fma.rn.f32x2 %0,%1,%2,%3;" : "=l"(r) : "l"(a), "l"(b), "l"(c)); return r;
}
__device__ __forceinline__ u64 mul2(u64 a, u64 b) {
    u64 r; asm("mul.rn.f32x2 %0,%1,%2;" : "=l"(r) : "l"(a), "l"(b)); return r;
}
__device__ __forceinline__ u64 swp2(u64 a) {
    float x, y; upk2(a, x, y); return pk2(y, x);
}
__device__ __forceinline__ u64 shflx2(u64 a, int m) {
    float x, y; upk2(a, x, y);
    x = __shfl_xor_sync(FULL, x, m);
    y = __shfl_xor_sync(FULL, y, m);
    return pk2(x, y);
}
__device__ __forceinline__ u64 shfli2(u64 a, int src) {
    float x, y; upk2(a, x, y);
    x = __shfl_sync(FULL, x, src);
    y = __shfl_sync(FULL, y, src);
    return pk2(x, y);
}

// ---- grid-uniform gate-constant table (written by prep kernel) ----
// lane[q]  (q0..q4): {cy, sy, cz, sz}
// jc[q-5]  (q5..q8): {cyv, syv, nsyv, czv, szv, nszv}  (packed dup pairs)
// pk[]     (q9):     {cyv, svec(-sy,sy), szpk(sz,-sz), szpkn(-sz,sz), czv}
struct GateTab {
    float4 lane[5];
    u64 jc[4][6];
    u64 pk[6];
};
__device__ GateTab g_tab[NL];

__global__ void prep_kernel(const float* __restrict__ params) {
    const int t = threadIdx.x;
    if (t >= NL * NQ) return;
    const int l = t / NQ, q = t % NQ;
    const float* p = params + l * (2 * NQ);
    const float hy = 0.5f * p[q];
    const float hz = 0.5f * p[NQ + q];
    float cy, sy, cz, sz;
    __sincosf(hy, &sy, &cy);
    __sincosf(hz, &sz, &cz);
    if (q <= 4) {
        g_tab[l].lane[q] = make_float4(cy, sy, cz, sz);
    } else if (q <= 8) {
        u64* jc = g_tab[l].jc[q - 5];
        jc[0] = pk2(cy, cy);  jc[1] = pk2(sy, sy);  jc[2] = pk2(-sy, -sy);
        jc[3] = pk2(cz, cz);  jc[4] = pk2(sz, sz);  jc[5] = pk2(-sz, -sz);
    } else {
        u64* pk = g_tab[l].pk;
        pk[0] = pk2(cy, cy);
        pk[1] = pk2(-sy, sy);
        pk[2] = pk2(sz, -sz);
        pk[3] = pk2(-sz, sz);
        pk[4] = pk2(cz, cz);
        pk[5] = 0ull;
    }
}

// State layout: amplitude index idx = (lane << 5) | (j << 1) | h, j = 0..15, h = 0/1.
//   qubit 0..4  -> lane bit (4 - q)
//   qubit 5..8  -> j bit    (8 - q)
//   qubit 9     -> packed half h (lo = 0, hi = 1)

// ---- fused RY (+optional RZ) on a j-bit qubit (q5..q8) ----
template<int JB, bool RZ>
__device__ __forceinline__ void ryrz_j(u64 (&Pr)[16], u64 (&Pi)[16], const u64* __restrict__ jc) {
    const u64 cyv  = __ldg(jc + 0);
    const u64 syv  = __ldg(jc + 1);
    const u64 nsyv = __ldg(jc + 2);
    u64 czv = 0, szv = 0, nszv = 0;
    if constexpr (RZ) { czv = __ldg(jc + 3); szv = __ldg(jc + 4); nszv = __ldg(jc + 5); }
#pragma unroll
    for (int j0 = 0; j0 < 16; ++j0) {
        if (j0 & (1 << JB)) continue;
        const int j1 = j0 | (1 << JB);
        u64 t0r = fma2(cyv, Pr[j0], mul2(nsyv, Pr[j1]));
        u64 t0i = fma2(cyv, Pi[j0], mul2(nsyv, Pi[j1]));
        u64 t1r = fma2(syv, Pr[j0], mul2(cyv, Pr[j1]));
        u64 t1i = fma2(syv, Pi[j0], mul2(cyv, Pi[j1]));
        if constexpr (RZ) {
            Pr[j0] = fma2(czv, t0r, mul2(szv,  t0i));
            Pi[j0] = fma2(czv, t0i, mul2(nszv, t0r));
            Pr[j1] = fma2(czv, t1r, mul2(nszv, t1i));
            Pi[j1] = fma2(czv, t1i, mul2(szv,  t1r));
        } else {
            Pr[j0] = t0r; Pi[j0] = t0i;
            Pr[j1] = t1r; Pi[j1] = t1i;
        }
    }
}

// ---- fused RY (+optional RZ) on qubit 9 (the packed dimension) ----
template<bool RZ>
__device__ __forceinline__ void ryrz_pk(u64 (&Pr)[16], u64 (&Pi)[16], const u64* __restrict__ pk) {
    const u64 cyv  = __ldg(pk + 0);
    const u64 svec = __ldg(pk + 1);
    u64 szpk = 0, szpkn = 0, czv = 0;
    if constexpr (RZ) { szpk = __ldg(pk + 2); szpkn = __ldg(pk + 3); czv = __ldg(pk + 4); }
#pragma unroll
    for (int j = 0; j < 16; ++j) {
        u64 sr = swp2(Pr[j]);
        u64 si = swp2(Pi[j]);
        u64 tr = fma2(cyv, Pr[j], mul2(svec, sr));
        u64 ti = fma2(cyv, Pi[j], mul2(svec, si));
        if constexpr (RZ) {
            Pr[j] = fma2(czv, tr, mul2(szpk,  ti));
            Pi[j] = fma2(czv, ti, mul2(szpkn, tr));
        } else {
            Pr[j] = tr; Pi[j] = ti;
        }
    }
}

// ---- fused RY (+optional RZ) on a lane-bit qubit (q0..q4) ----
template<int LB, bool RZ>
__device__ __forceinline__ void ryrz_lane(u64 (&Pr)[16], u64 (&Pi)[16],
                                          const float4* __restrict__ lc, int lane) {
    const float4 t = __ldg(lc);
    const int m = 1 << LB;
    const bool hi = (lane & m) != 0;
    const float ss = hi ?  t.y : -t.y;
    const float pz = hi ?  t.w : -t.w;
    const u64 cyv = pk2(t.x, t.x), ssv = pk2(ss, ss);
    const u64 czv = pk2(t.z, t.z), pzv = pk2(pz, pz), npzv = pk2(-pz, -pz);
#pragma unroll
    for (int j = 0; j < 16; ++j) {
        u64 prv = shflx2(Pr[j], m);
        u64 piv = shflx2(Pi[j], m);
        u64 tr = fma2(cyv, Pr[j], mul2(ssv, prv));
        u64 ti = fma2(cyv, Pi[j], mul2(ssv, piv));
        if constexpr (RZ) {
            Pr[j] = fma2(czv, tr, mul2(npzv, ti));
            Pi[j] = fma2(czv, ti, mul2(pzv,  tr));
        } else {
            Pr[j] = tr; Pi[j] = ti;
        }
    }
}

// ---- composed CNOT(0,1)(1,2)(2,3)(3,4): single lane permutation ----
__device__ __forceinline__ void cnot_lane_ring(u64 (&Pr)[16], u64 (&Pi)[16], int lane) {
    const int src = lane ^ ((lane >> 1) & 0xF);
#pragma unroll
    for (int j = 0; j < 16; ++j) {
        Pr[j] = shfli2(Pr[j], src);
        Pi[j] = shfli2(Pi[j], src);
    }
}

__device__ __forceinline__ void cnot_lj_c4(u64 (&Pr)[16], u64 (&Pi)[16], int lane) {
    if (lane & 1) {
#pragma unroll
        for (int j = 0; j < 8; ++j) {
            u64 t = Pr[j]; Pr[j] = Pr[j | 8]; Pr[j | 8] = t;
            u64 u = Pi[j]; Pi[j] = Pi[j | 8]; Pi[j | 8] = u;
        }
    }
}

template<int JC, int JT>
__device__ __forceinline__ void cnot_jj(u64 (&Pr)[16], u64 (&Pi)[16]) {
#pragma unroll
    for (int j = 0; j < 16; ++j) {
        if ((j & (1 << JC)) && !(j & (1 << JT))) {
            const int j1 = j | (1 << JT);
            u64 t = Pr[j]; Pr[j] = Pr[j1]; Pr[j1] = t;
            u64 u = Pi[j]; Pi[j] = Pi[j1]; Pi[j1] = u;
        }
    }
}

__device__ __forceinline__ void cnot_jp_c8(u64 (&Pr)[16], u64 (&Pi)[16]) {
#pragma unroll
    for (int j = 1; j < 16; j += 2) {
        Pr[j] = swp2(Pr[j]);
        Pi[j] = swp2(Pi[j]);
    }
}

__device__ __forceinline__ void cnot_pl_c9(u64 (&Pr)[16], u64 (&Pi)[16]) {
#pragma unroll
    for (int j = 0; j < 16; ++j) {
        float x, y; upk2(Pr[j], x, y);
        y = __shfl_xor_sync(FULL, y, 16);
        Pr[j] = pk2(x, y);
        float u, v; upk2(Pi[j], u, v);
        v = __shfl_xor_sync(FULL, v, 16);
        Pi[j] = pk2(u, v);
    }
}

template<bool RZ>
__device__ __forceinline__ void layer_rotations(u64 (&Pr)[16], u64 (&Pi)[16],
                                                const GateTab* __restrict__ tab, int lane) {
    ryrz_lane<4, RZ>(Pr, Pi, &tab->lane[0], lane);
    ryrz_lane<3, RZ>(Pr, Pi, &tab->lane[1], lane);
    ryrz_lane<2, RZ>(Pr, Pi, &tab->lane[2], lane);
    ryrz_lane<1, RZ>(Pr, Pi, &tab->lane[3], lane);
    ryrz_lane<0, RZ>(Pr, Pi, &tab->lane[4], lane);
    ryrz_j<3, RZ>(Pr, Pi, tab->jc[0]);
    ryrz_j<2, RZ>(Pr, Pi, tab->jc[1]);
    ryrz_j<1, RZ>(Pr, Pi, tab->jc[2]);
    ryrz_j<0, RZ>(Pr, Pi, tab->jc[3]);
    ryrz_pk<RZ>(Pr, Pi, tab->pk);
}

__device__ __forceinline__ void layer_cnots(u64 (&Pr)[16], u64 (&Pi)[16], int lane) {
    cnot_lane_ring(Pr, Pi, lane);   // CNOT(0,1)(1,2)(2,3)(3,4) composed
    cnot_lj_c4(Pr, Pi, lane);       // CNOT(4,5)
    cnot_jj<3, 2>(Pr, Pi);          // CNOT(5,6)
    cnot_jj<2, 1>(Pr, Pi);          // CNOT(6,7)
    cnot_jj<1, 0>(Pr, Pi);          // CNOT(7,8)
    cnot_jp_c8(Pr, Pi);             // CNOT(8,9)
    cnot_pl_c9(Pr, Pi);             // CNOT(9,0)
}

__global__ void __launch_bounds__(256)
pqc_kernel(const float* __restrict__ x, const float* __restrict__ params,
           float* __restrict__ out) {
    const int warp = (int)((blockIdx.x * blockDim.x + threadIdx.x) >> 5);
    const int lane = (int)(threadIdx.x & 31);

    // ======== init: encoding RY(x) fused with layer-0 RY(θy) + RZ(θz) ========
    float lf = 1.0f, phL = 0.0f;
#pragma unroll
    for (int q = 0; q <= 4; ++q) {
        const float hy = 0.5f * (__ldg(x + warp * NQ + q) + __ldg(params + q));
        const float tzq = 0.5f * __ldg(params + NQ + q);
        float cq, sq;
        __sincosf(hy, &sq, &cq);
        if ((lane >> (4 - q)) & 1) { lf *= sq; phL += tzq; }
        else                       { lf *= cq; phL -= tzq; }
    }

    float cs[5], ss[5], tzs[5];
#pragma unroll
    for (int q = 5; q <= 9; ++q) {
        const float hy = 0.5f * (__ldg(x + warp * NQ + q) + __ldg(params + q));
        __sincosf(hy, &ss[q - 5], &cs[q - 5]);
        tzs[q - 5] = 0.5f * __ldg(params + NQ + q);
    }

    float c9z, s9z;
    __sincosf(tzs[4], &s9z, &c9z);

    u64 Pr[16], Pi[16];
#pragma unroll
    for (int j = 0; j < 16; ++j) {
        float f = lf, ph = phL;           // j bit JB -> qubit (8 - JB)
#pragma unroll
        for (int JB = 0; JB < 4; ++JB) {
            const int i = 3 - JB;         // qubit (5 + i)
            if ((j >> JB) & 1) { f *= ss[i]; ph += tzs[i]; }
            else               { f *= cs[i]; ph -= tzs[i]; }
        }
        float cp, sp;
        __sincosf(ph, &sp, &cp);
        const float re0 = fmaf(cp, c9z,  sp * s9z);
        const float im0 = fmaf(sp, c9z, -(cp * s9z));
        const float re1 = fmaf(cp, c9z, -(sp * s9z));
        const float im1 = fmaf(sp, c9z,  cp * s9z);
        const float f0 = f * cs[4], f1 = f * ss[4];
        Pr[j] = pk2(f0 * re0, f1 * re1);
        Pi[j] = pk2(f0 * im0, f1 * im1);
    }
    // layer 0's CNOT ring still applies:
    layer_cnots(Pr, Pi, lane);

    // ======== middle layers ========
#pragma unroll 1
    for (int l = 1; l < NL - 1; ++l) {
        layer_rotations<true>(Pr, Pi, &g_tab[l], lane);
        layer_cnots(Pr, Pi, lane);
    }

    // ======== last layer: RY only; RZ + CNOT ring folded into measurement ========
    layer_rotations<false>(Pr, Pi, &g_tab[NL - 1], lane);

    // ======== measurement with CNOT-ring permutation folded into sign parities ========
    float psum = 0.0f, A = 0.0f;
    float S5 = 0.0f, S6 = 0.0f, S7 = 0.0f, S8 = 0.0f;
#pragma unroll
    for (int j = 0; j < 16; ++j) {
        u64 pp = fma2(Pr[j], Pr[j], mul2(Pi[j], Pi[j]));
        float plo, phi; upk2(pp, plo, phi);
        const float T = plo + phi;
        const float D = plo - phi;
        psum += T;
        A  += (__popc(j)      & 1) ? -D : D;
        S5 += ((j >> 3)       & 1) ? -T : T;
        S6 += (__popc(j >> 2) & 1) ? -T : T;
        S7 += (__popc(j >> 1) & 1) ? -T : T;
        S8 += (__popc(j)      & 1) ? -T : T;
    }

    const int lp = __popc(lane) & 1;
    float resv[NQ];
    resv[0] = ((lp ^ (lane >> 4)) & 1) ? -A : A;
    resv[1] = (__popc(lane >> 3) & 1) ? -psum : psum;
    resv[2] = (__popc(lane >> 2) & 1) ? -psum : psum;
    resv[3] = (__popc(lane >> 1) & 1) ? -psum : psum;
    resv[4] = lp ? -psum : psum;
    resv[5] = lp ? -S5 : S5;
    resv[6] = lp ? -S6 : S6;
    resv[7] = lp ? -S7 : S7;
    resv[8] = lp ? -S8 : S8;
    resv[9] = lp ? -A  : A;

#pragma unroll
    for (int q = 0; q < NQ; ++q) {
        float v = resv[q];
#pragma unroll
        for (int o = 16; o > 0; o >>= 1) v += __shfl_xor_sync(FULL, v, o);
        resv[q] = v;
    }

    if (lane == 0) {
#pragma unroll
        for (int q = 0; q < NQ; ++q)
            out[warp * NQ + q] = resv[q];
    }
}

extern "C" void kernel_launch(void* const* d_in, const int* in_sizes, int n_in,
                              void* d_out, int out_size) {
    const float* x      = (const float*)d_in[0];   // [4096, 10] float32
    const float* params = (const float*)d_in[1];   // [4, 20] float32
    float* out          = (float*)d_out;           // [4096, 10] float32
    (void)in_sizes; (void)n_in; (void)out_size;
    prep_kernel<<<1, 64>>>(params);
    pqc_kernel<<<BATCH / 8, 256>>>(x, params, out);
}

// round 13
// speedup vs baseline: 1.8028x; 1.5094x over previous
#include <cuda_runtime.h>

#define NQ 10
#define NL 4
#define BATCH 4096
#define FULL 0xFFFFFFFFu

typedef unsigned long long u64;

// ---- f32x2 packed-math primitives (sm_103a) ----
__device__ __forceinline__ u64 pk2(float lo, float hi) {
    u64 r; asm("mov.b64 %0,{%1,%2};" : "=l"(r) : "f"(lo), "f"(hi)); return r;
}
__device__ __forceinline__ void upk2(u64 a, float& lo, float& hi) {
    asm("mov.b64 {%0,%1},%2;" : "=f"(lo), "=f"(hi) : "l"(a));
}
__device__ __forceinline__ u64 fma2(u64 a, u64 b, u64 c) {
    u64 r; asm("fma.rn.f32x2 %0,%1,%2,%3;" : "=l"(r) : "l"(a), "l"(b), "l"(c)); return r;
}
__device__ __forceinline__ u64 mul2(u64 a, u64 b) {
    u64 r; asm("mul.rn.f32x2 %0,%1,%2;" : "=l"(r) : "l"(a), "l"(b)); return r;
}
__device__ __forceinline__ u64 swp2(u64 a) {
    float x, y; upk2(a, x, y); return pk2(y, x);
}
__device__ __forceinline__ u64 shflx2(u64 a, int m) {
    float x, y; upk2(a, x, y);
    x = __shfl_xor_sync(FULL, x, m);
    y = __shfl_xor_sync(FULL, y, m);
    return pk2(x, y);
}
__device__ __forceinline__ u64 shfli2(u64 a, int src) {
    float x, y; upk2(a, x, y);
    x = __shfl_sync(FULL, x, src);
    y = __shfl_sync(FULL, y, src);
    return pk2(x, y);
}

// Named barrier over one warp-pair (64 threads). ids 1..4 within the block.
__device__ __forceinline__ void barpair(int pair) {
    asm volatile("bar.sync %0, 64;" :: "r"(pair + 1) : "memory");
}

// ===== State layout (2 warps per sample) =====
// amplitude index: b0 = W (warp-of-pair), b1..b5 = lane bits 4..0,
//                  b6..b8 = j bits 2..0, b9 = packed half h (lo=0, hi=1).
// Per thread: Pr[8], Pi[8] (u64 = f32x2 over h). 32 regs of state.

// ---- fused RY (+opt RZ) on a lane-bit qubit (q1..q5) ----
template<int LB, bool RZ>
__device__ __forceinline__ void ryrz_lane8(u64 (&Pr)[8], u64 (&Pi)[8],
                                           const float* __restrict__ p, int q, int lane) {
    float cy, sy, cz, sz;
    __sincosf(0.5f * __ldg(p + q),      &sy, &cy);
    __sincosf(0.5f * __ldg(p + NQ + q), &sz, &cz);
    const int m = 1 << LB;
    const bool hi = (lane & m) != 0;
    const float ss = hi ?  sy : -sy;
    const float pz = hi ?  sz : -sz;
    const u64 cyv = pk2(cy, cy), ssv = pk2(ss, ss);
    const u64 czv = pk2(cz, cz), pzv = pk2(pz, pz), npzv = pk2(-pz, -pz);
#pragma unroll
    for (int j = 0; j < 8; ++j) {
        u64 prv = shflx2(Pr[j], m);
        u64 piv = shflx2(Pi[j], m);
        u64 tr = fma2(cyv, Pr[j], mul2(ssv, prv));
        u64 ti = fma2(cyv, Pi[j], mul2(ssv, piv));
        if constexpr (RZ) {
            Pr[j] = fma2(czv, tr, mul2(npzv, ti));
            Pi[j] = fma2(czv, ti, mul2(pzv,  tr));
        } else { Pr[j] = tr; Pi[j] = ti; }
    }
}

// ---- fused RY (+opt RZ) on a j-bit qubit (q6..q8) ----
template<int JB, bool RZ>
__device__ __forceinline__ void ryrz_j8(u64 (&Pr)[8], u64 (&Pi)[8],
                                        const float* __restrict__ p, int q) {
    float cy, sy, cz, sz;
    __sincosf(0.5f * __ldg(p + q),      &sy, &cy);
    __sincosf(0.5f * __ldg(p + NQ + q), &sz, &cz);
    const u64 cyv = pk2(cy, cy), syv = pk2(sy, sy), nsyv = pk2(-sy, -sy);
    const u64 czv = pk2(cz, cz), szv = pk2(sz, sz), nszv = pk2(-sz, -sz);
#pragma unroll
    for (int j0 = 0; j0 < 8; ++j0) {
        if (j0 & (1 << JB)) continue;
        const int j1 = j0 | (1 << JB);
        u64 t0r = fma2(cyv, Pr[j0], mul2(nsyv, Pr[j1]));
        u64 t0i = fma2(cyv, Pi[j0], mul2(nsyv, Pi[j1]));
        u64 t1r = fma2(syv, Pr[j0], mul2(cyv, Pr[j1]));
        u64 t1i = fma2(syv, Pi[j0], mul2(cyv, Pi[j1]));
        if constexpr (RZ) {
            Pr[j0] = fma2(czv, t0r, mul2(szv,  t0i));
            Pi[j0] = fma2(czv, t0i, mul2(nszv, t0r));
            Pr[j1] = fma2(czv, t1r, mul2(nszv, t1i));
            Pi[j1] = fma2(czv, t1i, mul2(szv,  t1r));
        } else {
            Pr[j0] = t0r; Pi[j0] = t0i;
            Pr[j1] = t1r; Pi[j1] = t1i;
        }
    }
}

// ---- fused RY (+opt RZ) on qubit 9 (the packed dimension) ----
template<bool RZ>
__device__ __forceinline__ void ryrz_pk8(u64 (&Pr)[8], u64 (&Pi)[8],
                                         const float* __restrict__ p) {
    float cy, sy, cz, sz;
    __sincosf(0.5f * __ldg(p + 9),      &sy, &cy);
    __sincosf(0.5f * __ldg(p + NQ + 9), &sz, &cz);
    const u64 cyv   = pk2(cy, cy);
    const u64 svec  = pk2(-sy,  sy);
    const u64 szpk  = pk2( sz, -sz);
    const u64 szpkn = pk2(-sz,  sz);
    const u64 czv   = pk2(cz, cz);
#pragma unroll
    for (int j = 0; j < 8; ++j) {
        u64 sr = swp2(Pr[j]);
        u64 si = swp2(Pi[j]);
        u64 tr = fma2(cyv, Pr[j], mul2(svec, sr));
        u64 ti = fma2(cyv, Pi[j], mul2(svec, si));
        if constexpr (RZ) {
            Pr[j] = fma2(czv, tr, mul2(szpk,  ti));
            Pi[j] = fma2(czv, ti, mul2(szpkn, tr));
        } else { Pr[j] = tr; Pi[j] = ti; }
    }
}

// ---- cross-warp fused RY (+opt RZ) on qubit 0 (warp-pair bit) ----
template<bool RZ>
__device__ __forceinline__ void ryrz_xwarp(u64 (&Pr)[8], u64 (&Pi)[8],
                                           const float* __restrict__ p,
                                           u64* __restrict__ xb, int t64, int W, int pair) {
    float cy, sy, cz, sz;
    __sincosf(0.5f * __ldg(p + 0),      &sy, &cy);
    __sincosf(0.5f * __ldg(p + NQ + 0), &sz, &cz);
    // snapshot own state (value-major layout: conflict-free)
#pragma unroll
    for (int k = 0; k < 8; ++k) xb[k * 64 + t64] = Pr[k];
#pragma unroll
    for (int k = 0; k < 8; ++k) xb[(8 + k) * 64 + t64] = Pi[k];
    barpair(pair);
    const float ss = W ?  sy : -sy;
    const float pz = W ?  sz : -sz;
    const u64 cyv = pk2(cy, cy), ssv = pk2(ss, ss);
    const u64 czv = pk2(cz, cz), pzv = pk2(pz, pz), npzv = pk2(-pz, -pz);
    const int pt = t64 ^ 32;
#pragma unroll
    for (int j = 0; j < 8; ++j) {
        u64 ppr = xb[j * 64 + pt];
        u64 ppi = xb[(8 + j) * 64 + pt];
        u64 tr = fma2(cyv, Pr[j], mul2(ssv, ppr));
        u64 ti = fma2(cyv, Pi[j], mul2(ssv, ppi));
        if constexpr (RZ) {
            Pr[j] = fma2(czv, tr, mul2(npzv, ti));
            Pi[j] = fma2(czv, ti, mul2(pzv,  tr));
        } else { Pr[j] = tr; Pi[j] = ti; }
    }
    barpair(pair);   // buffer safe for next use
}

template<bool RZ>
__device__ __forceinline__ void layer_rot(u64 (&Pr)[8], u64 (&Pi)[8],
                                          const float* __restrict__ p,
                                          int lane, int W, int t64, int pair,
                                          u64* __restrict__ xb) {
    ryrz_xwarp<RZ>(Pr, Pi, p, xb, t64, W, pair);       // q0
    ryrz_lane8<4, RZ>(Pr, Pi, p, 1, lane);             // q1
    ryrz_lane8<3, RZ>(Pr, Pi, p, 2, lane);             // q2
    ryrz_lane8<2, RZ>(Pr, Pi, p, 3, lane);             // q3
    ryrz_lane8<1, RZ>(Pr, Pi, p, 4, lane);             // q4
    ryrz_lane8<0, RZ>(Pr, Pi, p, 5, lane);             // q5
    ryrz_j8<2, RZ>(Pr, Pi, p, 6);                      // q6
    ryrz_j8<1, RZ>(Pr, Pi, p, 7);                      // q7
    ryrz_j8<0, RZ>(Pr, Pi, p, 8);                      // q8
    ryrz_pk8<RZ>(Pr, Pi, p);                           // q9
}

__device__ __forceinline__ void layer_ring(u64 (&Pr)[8], u64 (&Pi)[8],
                                           int lane, int W, int t64, int pair,
                                           u64* __restrict__ xb) {
    // (0,1): control W -> flip lane bit 4 (warp-uniform branch)
    if (W) {
#pragma unroll
        for (int j = 0; j < 8; ++j) {
            Pr[j] = shflx2(Pr[j], 16);
            Pi[j] = shflx2(Pi[j], 16);
        }
    }
    // (1,2)(2,3)(3,4)(4,5) composed: src = lane ^ ((lane>>1)&0xF)
    {
        const int src = lane ^ ((lane >> 1) & 0xF);
#pragma unroll
        for (int j = 0; j < 8; ++j) {
            Pr[j] = shfli2(Pr[j], src);
            Pi[j] = shfli2(Pi[j], src);
        }
    }
    // (5,6): control lane bit 0 -> flip j bit 2
    if (lane & 1) {
#pragma unroll
        for (int j = 0; j < 4; ++j) {
            u64 t = Pr[j]; Pr[j] = Pr[j | 4]; Pr[j | 4] = t;
            u64 u = Pi[j]; Pi[j] = Pi[j | 4]; Pi[j | 4] = u;
        }
    }
    // (6,7): j bit2 control, bit1 target: swap 4<->6, 5<->7
    { u64 t; t = Pr[4]; Pr[4] = Pr[6]; Pr[6] = t;  t = Pi[4]; Pi[4] = Pi[6]; Pi[6] = t;
            t = Pr[5]; Pr[5] = Pr[7]; Pr[7] = t;  t = Pi[5]; Pi[5] = Pi[7]; Pi[7] = t; }
    // (7,8): j bit1 control, bit0 target: swap 2<->3, 6<->7
    { u64 t; t = Pr[2]; Pr[2] = Pr[3]; Pr[3] = t;  t = Pi[2]; Pi[2] = Pi[3]; Pi[3] = t;
            t = Pr[6]; Pr[6] = Pr[7]; Pr[7] = t;  t = Pi[6]; Pi[6] = Pi[7]; Pi[7] = t; }
    // (8,9): control j bit0 -> swap packed halves for odd j
#pragma unroll
    for (int j = 1; j < 8; j += 2) { Pr[j] = swp2(Pr[j]); Pi[j] = swp2(Pi[j]); }
    // (9,0): control h -> swap hi halves across the warp pair (via smem)
    {
        float* fb = (float*)xb;
#pragma unroll
        for (int j = 0; j < 8; ++j) { float lo, hi; upk2(Pr[j], lo, hi); fb[j * 64 + t64] = hi; }
#pragma unroll
        for (int j = 0; j < 8; ++j) { float lo, hi; upk2(Pi[j], lo, hi); fb[(8 + j) * 64 + t64] = hi; }
        barpair(pair);
        const int pt = t64 ^ 32;
#pragma unroll
        for (int j = 0; j < 8; ++j) { float lo, hi; upk2(Pr[j], lo, hi); Pr[j] = pk2(lo, fb[j * 64 + pt]); }
#pragma unroll
        for (int j = 0; j < 8; ++j) { float lo, hi; upk2(Pi[j], lo, hi); Pi[j] = pk2(lo, fb[(8 + j) * 64 + pt]); }
        barpair(pair);
    }
}

__global__ void __launch_bounds__(256, 3)
pqc_kernel(const float* __restrict__ x, const float* __restrict__ params,
           float* __restrict__ out) {
    __shared__ u64 xbuf[4][16][64];        // 32 KB: per-pair exchange buffers
    __shared__ float red[4][2][10];        // reduction handoff

    const int tid  = (int)threadIdx.x;
    const int lane = tid & 31;
    const int W    = (tid >> 5) & 1;
    const int t64  = tid & 63;
    const int pair = tid >> 6;
    const int sample = (int)blockIdx.x * 4 + pair;
    u64* xb = &xbuf[pair][0][0];

    // ======== init: encoding RY(x) fused with layer-0 RY(θy) + RZ(θz) ========
    const float* xs = x + sample * NQ;
    float lf = 1.0f, phL = 0.0f;
    {   // qubit 0 -> W bit
        float cq, sq;
        __sincosf(0.5f * (__ldg(xs + 0) + __ldg(params + 0)), &sq, &cq);
        const float tz = 0.5f * __ldg(params + NQ + 0);
        if (W) { lf *= sq; phL += tz; } else { lf *= cq; phL -= tz; }
    }
#pragma unroll
    for (int q = 1; q <= 5; ++q) {         // qubit q -> lane bit (5-q)
        float cq, sq;
        __sincosf(0.5f * (__ldg(xs + q) + __ldg(params + q)), &sq, &cq);
        const float tz = 0.5f * __ldg(params + NQ + q);
        if ((lane >> (5 - q)) & 1) { lf *= sq; phL += tz; }
        else                       { lf *= cq; phL -= tz; }
    }
    float cs[3], ss[3], tzs[3];
#pragma unroll
    for (int q = 6; q <= 8; ++q) {
        __sincosf(0.5f * (__ldg(xs + q) + __ldg(params + q)), &ss[q - 6], &cs[q - 6]);
        tzs[q - 6] = 0.5f * __ldg(params + NQ + q);
    }
    float c9, s9;
    __sincosf(0.5f * (__ldg(xs + 9) + __ldg(params + 9)), &s9, &c9);
    float c9z, s9z;
    __sincosf(0.5f * __ldg(params + NQ + 9), &s9z, &c9z);

    u64 Pr[8], Pi[8];
#pragma unroll
    for (int j = 0; j < 8; ++j) {
        float f = lf, ph = phL;            // j bit JB -> qubit (8-JB) -> arr idx (2-JB)
#pragma unroll
        for (int JB = 0; JB < 3; ++JB) {
            const int i = 2 - JB;
            if ((j >> JB) & 1) { f *= ss[i]; ph += tzs[i]; }
            else               { f *= cs[i]; ph -= tzs[i]; }
        }
        float cp, sp;
        __sincosf(ph, &sp, &cp);
        const float re0 = fmaf(cp, c9z,  sp * s9z);
        const float im0 = fmaf(sp, c9z, -(cp * s9z));
        const float re1 = fmaf(cp, c9z, -(sp * s9z));
        const float im1 = fmaf(sp, c9z,  cp * s9z);
        const float f0 = f * c9, f1 = f * s9;
        Pr[j] = pk2(f0 * re0, f1 * re1);
        Pi[j] = pk2(f0 * im0, f1 * im1);
    }
    // layer 0's CNOT ring still applies
    layer_ring(Pr, Pi, lane, W, t64, pair, xb);

    // ======== middle layers ========
#pragma unroll 1
    for (int l = 1; l < NL - 1; ++l) {
        const float* p = params + l * (2 * NQ);
        layer_rot<true>(Pr, Pi, p, lane, W, t64, pair, xb);
        layer_ring(Pr, Pi, lane, W, t64, pair, xb);
    }

    // ======== last layer: RY only; RZ + final CNOT ring folded into measurement ========
    layer_rot<false>(Pr, Pi, params + (NL - 1) * (2 * NQ), lane, W, t64, pair, xb);

    // ======== measurement with final ring folded into sign parities ========
    // b'_0 = parity(b1..b9); b'_q = parity(b0..b_q) for q>=1
    float psum = 0.0f, A = 0.0f, S6 = 0.0f, S7 = 0.0f, S8 = 0.0f;
#pragma unroll
    for (int j = 0; j < 8; ++j) {
        u64 pp = fma2(Pr[j], Pr[j], mul2(Pi[j], Pi[j]));
        float plo, phi; upk2(pp, plo, phi);
        const float T = plo + phi;
        const float D = plo - phi;
        psum += T;
        A  += (__popc(j)      & 1) ? -D : D;
        S6 += ((j >> 2)       & 1) ? -T : T;
        S7 += (__popc(j >> 1) & 1) ? -T : T;
        S8 += (__popc(j)      & 1) ? -T : T;
    }

    const int pl = __popc(lane) & 1;       // parity of qubits 1..5
    const int wp = W ^ pl;
    float resv[NQ];
    resv[0] = pl ? -A : A;                                   // parity(b1..b9) via A
    resv[1] = (W ^ ((lane >> 4) & 1))        ? -psum : psum;
    resv[2] = (W ^ (__popc(lane >> 3) & 1))  ? -psum : psum;
    resv[3] = (W ^ (__popc(lane >> 2) & 1))  ? -psum : psum;
    resv[4] = (W ^ (__popc(lane >> 1) & 1))  ? -psum : psum;
    resv[5] = wp ? -psum : psum;
    resv[6] = wp ? -S6 : S6;
    resv[7] = wp ? -S7 : S7;
    resv[8] = wp ? -S8 : S8;
    resv[9] = wp ? -A  : A;

#pragma unroll
    for (int q = 0; q < NQ; ++q) {
        float v = resv[q];
#pragma unroll
        for (int o = 16; o > 0; o >>= 1) v += __shfl_xor_sync(FULL, v, o);
        resv[q] = v;
    }

    if (lane == 0) {
#pragma unroll
        for (int q = 0; q < NQ; ++q) red[pair][W][q] = resv[q];
    }
    barpair(pair);
    if (W == 0 && lane < NQ)
        out[sample * NQ + lane] = red[pair][0][lane] + red[pair][1][lane];
}

extern "C" void kernel_launch(void* const* d_in, const int* in_sizes, int n_in,
                              void* d_out, int out_size) {
    const float* x      = (const float*)d_in[0];   // [4096, 10] float32
    const float* params = (const float*)d_in[1];   // [4, 20] float32
    float* out          = (float*)d_out;           // [4096, 10] float32
    (void)in_sizes; (void)n_in; (void)out_size;
    // 64 threads per sample -> 4 samples per 256-thread block
    pqc_kernel<<<BATCH / 4, 256>>>(x, params, out);
}